// round 16
// baseline (speedup 1.0000x reference)
#include <cuda_runtime.h>
#include <cstdint>

#define BATCH 256
#define N 64
#define DIM 768
#define KC 64
#define NCH 12
#define DP 65
#define LP 65
#define BIGV 1e9f
#define KINF 0xFFFFFFFFFFFFFFFFull

typedef unsigned long long u64;
typedef unsigned int u32;

__device__ float g_partials[BATCH * 4];
__device__ u32   g_done = 0;

__device__ __forceinline__ u64 u64min(u64 a, u64 b) { return a < b ? a : b; }
__device__ __forceinline__ u64 packkey(float v, int flat) {
    return (((u64)__float_as_uint(v)) << 32) | (unsigned)flat;
}
__device__ __forceinline__ u32 bf16x2(float x1, float x0) {
    u32 r; asm("cvt.rn.bf16x2.f32 %0, %1, %2;" : "=r"(r) : "f"(x1), "f"(x0)); return r;
}
__device__ __forceinline__ u32 smem_u32(const void* p) {
    u32 a;
    asm("{ .reg .u64 t; cvta.to.shared.u64 t, %1; cvt.u32.u64 %0, t; }" : "=r"(a) : "l"(p));
    return a;
}
__device__ __forceinline__ void mma_bf16(float* d, const u32* a, u32 b0, u32 b1) {
    asm volatile("mma.sync.aligned.m16n8k16.row.col.f32.bf16.bf16.f32 "
        "{%0,%1,%2,%3}, {%4,%5,%6,%7}, {%8,%9}, {%0,%1,%2,%3};"
        : "+f"(d[0]), "+f"(d[1]), "+f"(d[2]), "+f"(d[3])
        : "r"(a[0]), "r"(a[1]), "r"(a[2]), "r"(a[3]), "r"(b0), "r"(b1));
}
#define LDSM4(r, a) \
    asm volatile("ldmatrix.sync.aligned.m8n8.x4.shared.b16 {%0,%1,%2,%3}, [%4];" \
        : "=r"((r)[0]), "=r"((r)[1]), "=r"((r)[2]), "=r"((r)[3]) : "r"(a))

__global__ __launch_bounds__(256, 2) void cluster_kernel(
    const float* __restrict__ q,
    const float* __restrict__ p,
    const int* __restrict__ labels_g,
    float* __restrict__ out)
{
    // POOL: during GEMM = 2 row-major SW128 tiles [128 rows x 128B] (hi 0-63, lo 64-127);
    //       after GEMM  = D[64][65] (0..4159) + Lsm[64][65] (4160..8319)
    __shared__ __align__(16) u32   POOL[8320];     // 33.3 KB
    __shared__ __align__(16) float qs[DIM];        // 3 KB
    __shared__ u64   rowkey_sm[N];
    __shared__ float sqv[N];
    __shared__ int   lab_in[N];
    __shared__ int   lab_sh[N];
    __shared__ int   s_kmask;
    __shared__ int   s_islast;
    __shared__ float wred[8][4];

    const int tid  = threadIdx.x;
    const int wid  = tid >> 5;
    const int lane = tid & 31;
    const int b    = blockIdx.x;
    const float* pb = p + (size_t)b * N * DIM;
    const float* qb = q + (size_t)b * DIM;
    char* PB = reinterpret_cast<char*>(POOL);
    const u32 smb = smem_u32(POOL);

    if (tid < 192)
        *reinterpret_cast<float4*>(&qs[tid * 4]) =
            *reinterpret_cast<const float4*>(qb + tid * 4);
    if (tid < N) lab_in[tid] = labels_g[b * N + tid];
    if (tid == 0) s_kmask = 0;
    __syncthreads();
    if (tid < N) atomicOr(&s_kmask, 1 << lab_in[tid]);

    // producer mapping: 4 (row, kcf) pairs/thread; row-major swizzled byte offsets
    int rowE[4], kcfE[4], offH[4];
    #pragma unroll
    for (int e = 0; e < 4; e++) {
        int idx4 = tid + 256 * e;
        int row  = idx4 >> 4;
        int kcf  = (idx4 & 15) * 4;
        rowE[e] = row; kcfE[e] = kcf;
        offH[e] = row * 128 + ((((kcf >> 3) ^ (row & 7)) & 7) << 4) + ((kcf & 4) << 1);
    }

    // consumer split: warp owns M-tile pair (mtw: T, mtw+4: L) and 4 N-tiles
    const int half = wid >> 2;
    const int mtw  = wid & 3;
    const int colsel = lane >> 4;
    const int l7  = lane & 7;
    const int l15 = lane & 15;
    const u32 baseT  = (u32)((16 * mtw + l15) * 128);
    const u32 baseL  = baseT + 8192;
    const u32 baseB0 = (u32)((32 * half + l15) * 128);
    const u32 baseB1 = baseB0 + 2048;

    float dacc[2][4][4];
    #pragma unroll
    for (int ms = 0; ms < 2; ms++)
        #pragma unroll
        for (int j = 0; j < 4; j++)
            #pragma unroll
            for (int c = 0; c < 4; c++) dacc[ms][j][c] = 0.f;

    float4 pv[4];
    #pragma unroll
    for (int e = 0; e < 4; e++)
        pv[e] = *reinterpret_cast<const float4*>(pb + rowE[e] * DIM + kcfE[e]);
    // L2 prefetch chunk 1 (chunk 0 already in registers)
    #pragma unroll
    for (int e = 0; e < 4; e++)
        asm volatile("prefetch.global.L2 [%0];"
                     :: "l"(pb + rowE[e] * DIM + KC + kcfE[e]));

    // ---- GEMM: store(ch) -> prefetch(ch+1) + L2-prefetch(ch+2) -> sync -> consume(ch) ----
    #pragma unroll 1
    for (int ch = 0; ch < NCH; ch++) {
        const int bufo = (ch & 1) * 16384;
        char* FB = PB + bufo;
        #pragma unroll
        for (int e = 0; e < 4; e++) {
            const float4 qv = *reinterpret_cast<const float4*>(&qs[ch * KC + kcfE[e]]);
            float x0 = pv[e].x * qv.x, x1 = pv[e].y * qv.y,
                  x2 = pv[e].z * qv.z, x3 = pv[e].w * qv.w;
            u32 h01 = bf16x2(x1, x0);
            u32 h23 = bf16x2(x3, x2);
            float l0 = x0 - __uint_as_float(h01 << 16);
            float l1 = x1 - __uint_as_float(h01 & 0xFFFF0000u);
            float l2 = x2 - __uint_as_float(h23 << 16);
            float l3 = x3 - __uint_as_float(h23 & 0xFFFF0000u);
            u32 l01 = bf16x2(l1, l0);
            u32 l23 = bf16x2(l3, l2);
            asm volatile("st.shared.v2.b32 [%0], {%1,%2};"
                         :: "l"((void*)(FB + offH[e])), "r"(h01), "r"(h23) : "memory");
            asm volatile("st.shared.v2.b32 [%0], {%1,%2};"
                         :: "l"((void*)(FB + offH[e] + 8192)), "r"(l01), "r"(l23) : "memory");
        }
        if (ch + 1 < NCH) {
            #pragma unroll
            for (int e = 0; e < 4; e++)
                pv[e] = *reinterpret_cast<const float4*>(
                            pb + rowE[e] * DIM + (ch + 1) * KC + kcfE[e]);
        }
        if (ch + 2 < NCH) {
            #pragma unroll
            for (int e = 0; e < 4; e++)
                asm volatile("prefetch.global.L2 [%0];"
                             :: "l"(pb + rowE[e] * DIM + (ch + 2) * KC + kcfE[e]));
        }
        __syncthreads();

        const u32 tb = smb + (u32)bufo;
        #pragma unroll
        for (int ks = 0; ks < 4; ks++) {
            const u32 pblk = (u32)(((2 * ks + colsel) ^ l7) << 4);
            u32 aT[4], aL[4], bA[4], bB[4];
            LDSM4(aT, tb + baseT + pblk);
            LDSM4(aL, tb + baseL + pblk);
            LDSM4(bA, tb + baseB0 + pblk);
            LDSM4(bB, tb + baseB1 + pblk);
            // nt j: 0 -> {bA0,bA2}, 1 -> {bA1,bA3}, 2 -> {bB0,bB2}, 3 -> {bB1,bB3}
            mma_bf16(dacc[0][0], aT, bA[0], bA[2]);
            mma_bf16(dacc[1][0], aL, bA[0], bA[2]);
            mma_bf16(dacc[0][1], aT, bA[1], bA[3]);
            mma_bf16(dacc[1][1], aL, bA[1], bA[3]);
            mma_bf16(dacc[0][2], aT, bB[0], bB[2]);
            mma_bf16(dacc[1][2], aL, bB[0], bB[2]);
            mma_bf16(dacc[0][3], aT, bB[1], bB[3]);
            mma_bf16(dacc[1][3], aL, bB[1], bB[3]);
        }
    }
    __syncthreads();

    float (*D)[DP] = reinterpret_cast<float(*)[DP]>(POOL);
    float* Lsm = reinterpret_cast<float*>(POOL) + 4160;

    // C writeout: T (ms=0) -> D (lower-tri tiles land in never-read entries); L -> Lsm
    {
        int rb = lane >> 2;
        int cb = (lane & 3) * 2;
        #pragma unroll
        for (int j = 0; j < 4; j++) {
            int nt  = half * 4 + j;
            int col = nt * 8 + cb;
            int r0  = 16 * mtw + rb;
            D[r0][col]         = dacc[0][j][0];
            D[r0][col + 1]     = dacc[0][j][1];
            D[r0 + 8][col]     = dacc[0][j][2];
            D[r0 + 8][col + 1] = dacc[0][j][3];
            Lsm[r0 * LP + col]           = dacc[1][j][0];
            Lsm[r0 * LP + col + 1]       = dacc[1][j][1];
            Lsm[(r0 + 8) * LP + col]     = dacc[1][j][2];
            Lsm[(r0 + 8) * LP + col + 1] = dacc[1][j][3];
        }
    }
    __syncthreads();

    if (tid < N)
        sqv[tid] = (D[tid][tid] + Lsm[tid * LP + tid]) + Lsm[tid * LP + tid];
    __syncthreads();

    // ---- fused distances + sim/dis + rowkeys (4 threads/row, 16 cols each) ----
    float simN = 0.f, disN = 0.f, simC = 0.f;
    {
        const int row   = tid >> 2;
        const int cbase = (tid & 3) * 16;
        const int li    = lab_in[row];
        float dreg[16];
        #pragma unroll
        for (int s = 0; s < 16; s++) {
            int col = cbase + s;
            int lo = min(row, col), hi = max(row, col);
            float g = (D[lo][hi] + Lsm[lo * LP + hi]) + Lsm[hi * LP + lo];
            float d2 = sqv[row] + sqv[col] - 2.f * g;
            float dist = (d2 > 0.f) ? sqrtf(d2) : 0.f;
            bool sim = (li == lab_in[col]);
            simN += sim ? dist : 0.f;
            disN += sim ? 0.f : dist;
            simC += sim ? 1.f : 0.f;
            dreg[s] = (col == row) ? BIGV : dist;
        }
        __syncthreads();   // all T/L reads done before overwriting D
        u64 key = KINF;
        #pragma unroll
        for (int s = 0; s < 16; s++) {
            D[row][cbase + s] = dreg[s];
            key = u64min(key, packkey(dreg[s], row * 64 + cbase + s));
        }
        key = u64min(key, __shfl_down_sync(0xFFFFFFFFu, key, 2));
        key = u64min(key, __shfl_down_sync(0xFFFFFFFFu, key, 1));
        if ((tid & 3) == 0) rowkey_sm[row] = key;
    }
    __syncthreads();

    const int merges = N - __popc(s_kmask);

    // ---- single-linkage: warp 0, branch-free body, redux-converged (no syncwarp) ----
    if (tid < 32) {
        const int c0 = 2 * lane, c1 = c0 + 1;
        u64 rk0 = rowkey_sm[c0], rk1 = rowkey_sm[c1];
        u64 pend = KINF;
        u64 act = ~0ull;
        int aprev = -2;
        int lab0 = c0, lab1 = c1;

        #pragma unroll 1
        for (int m = 0; m < merges; m++) {
            u64 cand = u64min(u64min(rk0, rk1), pend);
            u32 chi = (u32)(cand >> 32);
            u32 h   = __reduce_min_sync(0xFFFFFFFFu, chi);
            u32 cl  = (chi == h) ? (u32)cand : 0xFFFFFFFFu;
            u32 l   = __reduce_min_sync(0xFFFFFFFFu, cl);
            u32 phi = (u32)(pend >> 32);
            u32 ph  = __reduce_min_sync(0xFFFFFFFFu, phi);
            u32 plo = (phi == ph) ? (u32)pend : 0xFFFFFFFFu;
            u32 pl  = __reduce_min_sync(0xFFFFFFFFu, plo);

            u64 pr = (((u64)ph) << 32) | pl;
            bool own = (lane == (aprev >> 1));
            bool odd = (aprev & 1);
            rk0 = (own & !odd) ? pr : rk0;
            rk1 = (own &  odd) ? pr : rk1;

            int flat = (int)l;
            int a = flat >> 6, bb = flat & 63;

            act &= ~(1ull << bb);

            float da0 = D[a][c0], db0 = D[bb][c0];
            float da1 = D[a][c1], db1 = D[bb][c1];
            float m0 = fminf(da0, db0);
            float m1 = fminf(da1, db1);
            D[a][c0] = m0; D[a][c1] = m1;
            D[c0][a] = m0; D[c1][a] = m1;

            bool a0 = (act >> c0) & 1ull;
            bool a1 = (act >> c1) & 1ull;
            bool live0 = a0 & (c0 != a);
            bool live1 = a1 & (c1 != a);
            u64 k0 = live0 ? packkey(m0, a * 64 + c0) : KINF;
            u64 k1 = live1 ? packkey(m1, a * 64 + c1) : KINF;
            pend = u64min(k0, k1);
            aprev = a;

            u64 r0 = ((int)(rk0 & 63ull) == bb) ? ((rk0 & ~63ull) | (unsigned)a) : rk0;
            r0 = u64min(r0, packkey(m0, c0 * 64 + a));
            u64 r1 = ((int)(rk1 & 63ull) == bb) ? ((rk1 & ~63ull) | (unsigned)a) : rk1;
            r1 = u64min(r1, packkey(m1, c1 * 64 + a));
            bool dead0 = (c0 == a) | (c0 == bb);
            bool dead1 = (c1 == a) | (c1 == bb);
            rk0 = dead0 ? KINF : (a0 ? r0 : rk0);
            rk1 = dead1 ? KINF : (a1 ? r1 : rk1);

            lab0 = (lab0 == bb) ? a : lab0;
            lab1 = (lab1 == bb) ? a : lab1;
        }
        lab_sh[c0] = lab0;
        lab_sh[c1] = lab1;
    }
    __syncthreads();

    float errC = 0.f;
    #pragma unroll
    for (int e = tid; e < 4096; e += 256) {
        int i = e >> 6, j = e & 63;
        bool adj = (lab_sh[i] == lab_sh[j]);
        bool tru = (lab_in[i] == lab_in[j]);
        errC += (adj != tru) ? 1.f : 0.f;
    }

    float v0 = simN, v1 = disN, v2 = simC, v3 = errC;
    #pragma unroll
    for (int o = 16; o > 0; o >>= 1) {
        v0 += __shfl_down_sync(0xFFFFFFFFu, v0, o);
        v1 += __shfl_down_sync(0xFFFFFFFFu, v1, o);
        v2 += __shfl_down_sync(0xFFFFFFFFu, v2, o);
        v3 += __shfl_down_sync(0xFFFFFFFFu, v3, o);
    }
    if (lane == 0) {
        wred[wid][0] = v0; wred[wid][1] = v1; wred[wid][2] = v2; wred[wid][3] = v3;
    }
    __syncthreads();
    if (tid == 0) {
        float a0 = 0.f, a1 = 0.f, a2 = 0.f, a3 = 0.f;
        #pragma unroll
        for (int w = 0; w < 8; w++) {
            a0 += wred[w][0]; a1 += wred[w][1]; a2 += wred[w][2]; a3 += wred[w][3];
        }
        g_partials[b * 4 + 0] = a0;
        g_partials[b * 4 + 1] = a1;
        g_partials[b * 4 + 2] = a2;
        g_partials[b * 4 + 3] = a3;
        __threadfence();
        u32 old = atomicAdd(&g_done, 1u);
        s_islast = (old == BATCH - 1);
        if (s_islast) g_done = 0;           // reset for next replay
    }
    __syncthreads();

    // ---- fused finalize: last CTA reduces all partials ----
    if (s_islast) {
        double s0 = (double)__ldcg(&g_partials[tid * 4 + 0]);
        double s1 = (double)__ldcg(&g_partials[tid * 4 + 1]);
        double s2 = (double)__ldcg(&g_partials[tid * 4 + 2]);
        double s3 = (double)__ldcg(&g_partials[tid * 4 + 3]);
        #pragma unroll
        for (int o = 16; o > 0; o >>= 1) {
            s0 += __shfl_down_sync(0xFFFFFFFFu, s0, o);
            s1 += __shfl_down_sync(0xFFFFFFFFu, s1, o);
            s2 += __shfl_down_sync(0xFFFFFFFFu, s2, o);
            s3 += __shfl_down_sync(0xFFFFFFFFu, s3, o);
        }
        double* dsh = reinterpret_cast<double*>(POOL);   // smem free now
        if (lane == 0) {
            dsh[wid * 4 + 0] = s0; dsh[wid * 4 + 1] = s1;
            dsh[wid * 4 + 2] = s2; dsh[wid * 4 + 3] = s3;
        }
        __syncthreads();
        if (tid == 0) {
            double simNt = 0.0, disNt = 0.0, simCt = 0.0, errCt = 0.0;
            #pragma unroll
            for (int w = 0; w < 8; w++) {
                simNt += dsh[w * 4 + 0]; disNt += dsh[w * 4 + 1];
                simCt += dsh[w * 4 + 2]; errCt += dsh[w * 4 + 3];
            }
            double disCt = (double)BATCH * N * N - simCt;
            double res = errCt / (double)BATCH + 0.5 * (simNt / simCt - disNt / disCt);
            out[0] = (float)res;
        }
    }
}

extern "C" void kernel_launch(void* const* d_in, const int* in_sizes, int n_in,
                              void* d_out, int out_size)
{
    const float* q   = (const float*)d_in[0];
    const float* p   = (const float*)d_in[1];
    const int*   lab = (const int*)d_in[2];
    (void)in_sizes; (void)n_in; (void)out_size;

    cluster_kernel<<<BATCH, 256>>>(q, p, lab, (float*)d_out);
}

// round 17
// speedup vs baseline: 1.0512x; 1.0512x over previous
#include <cuda_runtime.h>
#include <cstdint>

#define BATCH 256
#define N 64
#define DIM 768
#define KC 64
#define NCH 12
#define DP 65
#define LP 65
#define BIGV 1e9f
#define KINF 0xFFFFFFFFFFFFFFFFull

typedef unsigned long long u64;
typedef unsigned int u32;

__device__ float g_partials[BATCH * 4];
__device__ u32   g_done = 0;

__device__ __forceinline__ u64 u64min(u64 a, u64 b) { return a < b ? a : b; }
__device__ __forceinline__ u64 packkey(float v, int flat) {
    return (((u64)__float_as_uint(v)) << 32) | (unsigned)flat;
}
__device__ __forceinline__ u32 bf16x2(float x1, float x0) {
    u32 r; asm("cvt.rn.bf16x2.f32 %0, %1, %2;" : "=r"(r) : "f"(x1), "f"(x0)); return r;
}
__device__ __forceinline__ u32 smem_u32(const void* p) {
    u32 a;
    asm("{ .reg .u64 t; cvta.to.shared.u64 t, %1; cvt.u32.u64 %0, t; }" : "=r"(a) : "l"(p));
    return a;
}
__device__ __forceinline__ void mma_bf16(float* d, const u32* a, u32 b0, u32 b1) {
    asm volatile("mma.sync.aligned.m16n8k16.row.col.f32.bf16.bf16.f32 "
        "{%0,%1,%2,%3}, {%4,%5,%6,%7}, {%8,%9}, {%0,%1,%2,%3};"
        : "+f"(d[0]), "+f"(d[1]), "+f"(d[2]), "+f"(d[3])
        : "r"(a[0]), "r"(a[1]), "r"(a[2]), "r"(a[3]), "r"(b0), "r"(b1));
}
#define LDSM4(r, a) \
    asm volatile("ldmatrix.sync.aligned.m8n8.x4.shared.b16 {%0,%1,%2,%3}, [%4];" \
        : "=r"((r)[0]), "=r"((r)[1]), "=r"((r)[2]), "=r"((r)[3]) : "r"(a))

__global__ __launch_bounds__(256, 2) void cluster_kernel(
    const float* __restrict__ q,
    const float* __restrict__ p,
    const int* __restrict__ labels_g,
    float* __restrict__ out)
{
    // POOL: during GEMM = 2 row-major SW128 tiles [128 rows x 128B] (hi 0-63, lo 64-127);
    //       after GEMM  = D[64][65] (0..4159) + Lsm[64][65] (4160..8319)
    __shared__ __align__(16) u32   POOL[8320];     // 33.3 KB
    __shared__ __align__(16) float qs[DIM];        // 3 KB
    __shared__ u64   rowkey_sm[N];
    __shared__ float sqv[N];
    __shared__ int   lab_in[N];
    __shared__ int   lab_sh[N];
    __shared__ int   s_kmask;
    __shared__ int   s_islast;
    __shared__ float wred[8][4];

    const int tid  = threadIdx.x;
    const int wid  = tid >> 5;
    const int lane = tid & 31;
    const int b    = blockIdx.x;
    const float* pb = p + (size_t)b * N * DIM;
    const float* qb = q + (size_t)b * DIM;
    char* PB = reinterpret_cast<char*>(POOL);
    const u32 smb = smem_u32(POOL);

    if (tid < 192)
        *reinterpret_cast<float4*>(&qs[tid * 4]) =
            *reinterpret_cast<const float4*>(qb + tid * 4);
    if (tid < N) lab_in[tid] = labels_g[b * N + tid];
    if (tid == 0) s_kmask = 0;
    __syncthreads();
    if (tid < N) atomicOr(&s_kmask, 1 << lab_in[tid]);

    // producer mapping: 4 (row, kcf) pairs/thread; row-major swizzled byte offsets
    int rowE[4], kcfE[4], offH[4];
    #pragma unroll
    for (int e = 0; e < 4; e++) {
        int idx4 = tid + 256 * e;
        int row  = idx4 >> 4;
        int kcf  = (idx4 & 15) * 4;
        rowE[e] = row; kcfE[e] = kcf;
        offH[e] = row * 128 + ((((kcf >> 3) ^ (row & 7)) & 7) << 4) + ((kcf & 4) << 1);
    }

    // consumer split: warp owns M-tile pair (mtw: T, mtw+4: L) and 4 N-tiles
    const int half = wid >> 2;
    const int mtw  = wid & 3;
    const int colsel = lane >> 4;
    const int l7  = lane & 7;
    const int l15 = lane & 15;
    const u32 baseT  = (u32)((16 * mtw + l15) * 128);
    const u32 baseL  = baseT + 8192;
    const u32 baseB0 = (u32)((32 * half + l15) * 128);
    const u32 baseB1 = baseB0 + 2048;

    float dacc[2][4][4];
    #pragma unroll
    for (int ms = 0; ms < 2; ms++)
        #pragma unroll
        for (int j = 0; j < 4; j++)
            #pragma unroll
            for (int c = 0; c < 4; c++) dacc[ms][j][c] = 0.f;

    float4 pv[4];
    #pragma unroll
    for (int e = 0; e < 4; e++)
        pv[e] = *reinterpret_cast<const float4*>(pb + rowE[e] * DIM + kcfE[e]);

    // ---- GEMM: store(ch) -> prefetch(ch+1) -> sync -> consume(ch) ----
    #pragma unroll 1
    for (int ch = 0; ch < NCH; ch++) {
        const int bufo = (ch & 1) * 16384;
        char* FB = PB + bufo;
        #pragma unroll
        for (int e = 0; e < 4; e++) {
            const float4 qv = *reinterpret_cast<const float4*>(&qs[ch * KC + kcfE[e]]);
            float x0 = pv[e].x * qv.x, x1 = pv[e].y * qv.y,
                  x2 = pv[e].z * qv.z, x3 = pv[e].w * qv.w;
            u32 h01 = bf16x2(x1, x0);
            u32 h23 = bf16x2(x3, x2);
            float l0 = x0 - __uint_as_float(h01 << 16);
            float l1 = x1 - __uint_as_float(h01 & 0xFFFF0000u);
            float l2 = x2 - __uint_as_float(h23 << 16);
            float l3 = x3 - __uint_as_float(h23 & 0xFFFF0000u);
            u32 l01 = bf16x2(l1, l0);
            u32 l23 = bf16x2(l3, l2);
            asm volatile("st.shared.v2.b32 [%0], {%1,%2};"
                         :: "l"((void*)(FB + offH[e])), "r"(h01), "r"(h23) : "memory");
            asm volatile("st.shared.v2.b32 [%0], {%1,%2};"
                         :: "l"((void*)(FB + offH[e] + 8192)), "r"(l01), "r"(l23) : "memory");
        }
        if (ch + 1 < NCH) {
            #pragma unroll
            for (int e = 0; e < 4; e++)
                pv[e] = *reinterpret_cast<const float4*>(
                            pb + rowE[e] * DIM + (ch + 1) * KC + kcfE[e]);
        }
        __syncthreads();

        const u32 tb = smb + (u32)bufo;
        #pragma unroll
        for (int ks = 0; ks < 4; ks++) {
            const u32 pblk = (u32)(((2 * ks + colsel) ^ l7) << 4);
            u32 aT[4], aL[4], bA[4], bB[4];
            LDSM4(aT, tb + baseT + pblk);
            LDSM4(aL, tb + baseL + pblk);
            LDSM4(bA, tb + baseB0 + pblk);
            LDSM4(bB, tb + baseB1 + pblk);
            // nt j: 0 -> {bA0,bA2}, 1 -> {bA1,bA3}, 2 -> {bB0,bB2}, 3 -> {bB1,bB3}
            mma_bf16(dacc[0][0], aT, bA[0], bA[2]);
            mma_bf16(dacc[1][0], aL, bA[0], bA[2]);
            mma_bf16(dacc[0][1], aT, bA[1], bA[3]);
            mma_bf16(dacc[1][1], aL, bA[1], bA[3]);
            mma_bf16(dacc[0][2], aT, bB[0], bB[2]);
            mma_bf16(dacc[1][2], aL, bB[0], bB[2]);
            mma_bf16(dacc[0][3], aT, bB[1], bB[3]);
            mma_bf16(dacc[1][3], aL, bB[1], bB[3]);
        }
    }
    __syncthreads();

    float (*D)[DP] = reinterpret_cast<float(*)[DP]>(POOL);
    float* Lsm = reinterpret_cast<float*>(POOL) + 4160;

    // C writeout: T (ms=0) -> D (lower-tri tiles land in never-read entries); L -> Lsm
    {
        int rb = lane >> 2;
        int cb = (lane & 3) * 2;
        #pragma unroll
        for (int j = 0; j < 4; j++) {
            int nt  = half * 4 + j;
            int col = nt * 8 + cb;
            int r0  = 16 * mtw + rb;
            D[r0][col]         = dacc[0][j][0];
            D[r0][col + 1]     = dacc[0][j][1];
            D[r0 + 8][col]     = dacc[0][j][2];
            D[r0 + 8][col + 1] = dacc[0][j][3];
            Lsm[r0 * LP + col]           = dacc[1][j][0];
            Lsm[r0 * LP + col + 1]       = dacc[1][j][1];
            Lsm[(r0 + 8) * LP + col]     = dacc[1][j][2];
            Lsm[(r0 + 8) * LP + col + 1] = dacc[1][j][3];
        }
    }
    __syncthreads();

    if (tid < N)
        sqv[tid] = (D[tid][tid] + Lsm[tid * LP + tid]) + Lsm[tid * LP + tid];
    __syncthreads();

    // ---- fused distances + sim/dis + rowkeys (4 threads/row, 16 cols each) ----
    float simN = 0.f, disN = 0.f, simC = 0.f;
    {
        const int row   = tid >> 2;
        const int cbase = (tid & 3) * 16;
        const int li    = lab_in[row];
        float dreg[16];
        #pragma unroll
        for (int s = 0; s < 16; s++) {
            int col = cbase + s;
            int lo = min(row, col), hi = max(row, col);
            float g = (D[lo][hi] + Lsm[lo * LP + hi]) + Lsm[hi * LP + lo];
            float d2 = sqv[row] + sqv[col] - 2.f * g;
            float dist = (d2 > 0.f) ? sqrtf(d2) : 0.f;
            bool sim = (li == lab_in[col]);
            simN += sim ? dist : 0.f;
            disN += sim ? 0.f : dist;
            simC += sim ? 1.f : 0.f;
            dreg[s] = (col == row) ? BIGV : dist;
        }
        __syncthreads();   // all T/L reads done before overwriting D
        u64 key = KINF;
        #pragma unroll
        for (int s = 0; s < 16; s++) {
            D[row][cbase + s] = dreg[s];
            key = u64min(key, packkey(dreg[s], row * 64 + cbase + s));
        }
        key = u64min(key, __shfl_down_sync(0xFFFFFFFFu, key, 2));
        key = u64min(key, __shfl_down_sync(0xFFFFFFFFu, key, 1));
        if ((tid & 3) == 0) rowkey_sm[row] = key;
    }
    __syncthreads();

    const int merges = N - __popc(s_kmask);

    // ---- single-linkage: warp 0, branch-free body ----
    if (tid < 32) {
        const int c0 = 2 * lane, c1 = c0 + 1;
        u64 rk0 = rowkey_sm[c0], rk1 = rowkey_sm[c1];
        u64 pend = KINF;
        u64 act = ~0ull;
        int aprev = -2;
        int lab0 = c0, lab1 = c1;

        #pragma unroll 1
        for (int m = 0; m < merges; m++) {
            u64 cand = u64min(u64min(rk0, rk1), pend);
            u32 chi = (u32)(cand >> 32);
            u32 h   = __reduce_min_sync(0xFFFFFFFFu, chi);
            u32 cl  = (chi == h) ? (u32)cand : 0xFFFFFFFFu;
            u32 l   = __reduce_min_sync(0xFFFFFFFFu, cl);
            u32 phi = (u32)(pend >> 32);
            u32 ph  = __reduce_min_sync(0xFFFFFFFFu, phi);
            u32 plo = (phi == ph) ? (u32)pend : 0xFFFFFFFFu;
            u32 pl  = __reduce_min_sync(0xFFFFFFFFu, plo);

            u64 pr = (((u64)ph) << 32) | pl;
            bool own = (lane == (aprev >> 1));
            bool odd = (aprev & 1);
            rk0 = (own & !odd) ? pr : rk0;
            rk1 = (own &  odd) ? pr : rk1;

            int flat = (int)l;
            int a = flat >> 6, bb = flat & 63;

            act &= ~(1ull << bb);

            float da0 = D[a][c0], db0 = D[bb][c0];
            float da1 = D[a][c1], db1 = D[bb][c1];
            float m0 = fminf(da0, db0);
            float m1 = fminf(da1, db1);
            D[a][c0] = m0; D[a][c1] = m1;
            D[c0][a] = m0; D[c1][a] = m1;

            bool a0 = (act >> c0) & 1ull;
            bool a1 = (act >> c1) & 1ull;
            bool live0 = a0 & (c0 != a);
            bool live1 = a1 & (c1 != a);
            u64 k0 = live0 ? packkey(m0, a * 64 + c0) : KINF;
            u64 k1 = live1 ? packkey(m1, a * 64 + c1) : KINF;
            pend = u64min(k0, k1);
            aprev = a;

            u64 r0 = ((int)(rk0 & 63ull) == bb) ? ((rk0 & ~63ull) | (unsigned)a) : rk0;
            r0 = u64min(r0, packkey(m0, c0 * 64 + a));
            u64 r1 = ((int)(rk1 & 63ull) == bb) ? ((rk1 & ~63ull) | (unsigned)a) : rk1;
            r1 = u64min(r1, packkey(m1, c1 * 64 + a));
            bool dead0 = (c0 == a) | (c0 == bb);
            bool dead1 = (c1 == a) | (c1 == bb);
            rk0 = dead0 ? KINF : (a0 ? r0 : rk0);
            rk1 = dead1 ? KINF : (a1 ? r1 : rk1);

            lab0 = (lab0 == bb) ? a : lab0;
            lab1 = (lab1 == bb) ? a : lab1;
            __syncwarp();
        }
        lab_sh[c0] = lab0;
        lab_sh[c1] = lab1;
    }
    __syncthreads();

    float errC = 0.f;
    #pragma unroll
    for (int e = tid; e < 4096; e += 256) {
        int i = e >> 6, j = e & 63;
        bool adj = (lab_sh[i] == lab_sh[j]);
        bool tru = (lab_in[i] == lab_in[j]);
        errC += (adj != tru) ? 1.f : 0.f;
    }

    float v0 = simN, v1 = disN, v2 = simC, v3 = errC;
    #pragma unroll
    for (int o = 16; o > 0; o >>= 1) {
        v0 += __shfl_down_sync(0xFFFFFFFFu, v0, o);
        v1 += __shfl_down_sync(0xFFFFFFFFu, v1, o);
        v2 += __shfl_down_sync(0xFFFFFFFFu, v2, o);
        v3 += __shfl_down_sync(0xFFFFFFFFu, v3, o);
    }
    if (lane == 0) {
        wred[wid][0] = v0; wred[wid][1] = v1; wred[wid][2] = v2; wred[wid][3] = v3;
    }
    __syncthreads();
    if (tid == 0) {
        float a0 = 0.f, a1 = 0.f, a2 = 0.f, a3 = 0.f;
        #pragma unroll
        for (int w = 0; w < 8; w++) {
            a0 += wred[w][0]; a1 += wred[w][1]; a2 += wred[w][2]; a3 += wred[w][3];
        }
        g_partials[b * 4 + 0] = a0;
        g_partials[b * 4 + 1] = a1;
        g_partials[b * 4 + 2] = a2;
        g_partials[b * 4 + 3] = a3;
        __threadfence();
        u32 old = atomicAdd(&g_done, 1u);
        s_islast = (old == BATCH - 1);
        if (s_islast) g_done = 0;           // reset for next replay
    }
    __syncthreads();

    // ---- fused finalize: last CTA reduces all partials ----
    if (s_islast) {
        double s0 = (double)__ldcg(&g_partials[tid * 4 + 0]);
        double s1 = (double)__ldcg(&g_partials[tid * 4 + 1]);
        double s2 = (double)__ldcg(&g_partials[tid * 4 + 2]);
        double s3 = (double)__ldcg(&g_partials[tid * 4 + 3]);
        #pragma unroll
        for (int o = 16; o > 0; o >>= 1) {
            s0 += __shfl_down_sync(0xFFFFFFFFu, s0, o);
            s1 += __shfl_down_sync(0xFFFFFFFFu, s1, o);
            s2 += __shfl_down_sync(0xFFFFFFFFu, s2, o);
            s3 += __shfl_down_sync(0xFFFFFFFFu, s3, o);
        }
        double* dsh = reinterpret_cast<double*>(POOL);   // smem free now
        if (lane == 0) {
            dsh[wid * 4 + 0] = s0; dsh[wid * 4 + 1] = s1;
            dsh[wid * 4 + 2] = s2; dsh[wid * 4 + 3] = s3;
        }
        __syncthreads();
        if (tid == 0) {
            double simNt = 0.0, disNt = 0.0, simCt = 0.0, errCt = 0.0;
            #pragma unroll
            for (int w = 0; w < 8; w++) {
                simNt += dsh[w * 4 + 0]; disNt += dsh[w * 4 + 1];
                simCt += dsh[w * 4 + 2]; errCt += dsh[w * 4 + 3];
            }
            double disCt = (double)BATCH * N * N - simCt;
            double res = errCt / (double)BATCH + 0.5 * (simNt / simCt - disNt / disCt);
            out[0] = (float)res;
        }
    }
}

extern "C" void kernel_launch(void* const* d_in, const int* in_sizes, int n_in,
                              void* d_out, int out_size)
{
    const float* q   = (const float*)d_in[0];
    const float* p   = (const float*)d_in[1];
    const int*   lab = (const int*)d_in[2];
    (void)in_sizes; (void)n_in; (void)out_size;

    cluster_kernel<<<BATCH, 256>>>(q, p, lab, (float*)d_out);
}